// round 5
// baseline (speedup 1.0000x reference)
#include <cuda_runtime.h>
#include <stdint.h>

#define TT 64          // num types
#define CC 128         // channels
#define TC (TT * CC)   // 8192 stat entries

// ---- device scratch (no allocations allowed) ----
__device__ float2 g_acc[TC];   // {sum, sumsq}
__device__ float  g_cnt[TT];
__device__ float  g_mean[TC];
__device__ float  g_rstd[TC];
__device__ int    g_is64;

// ---------------------------------------------------------------------------
// Kernel 0: zero accumulators + detect int64-vs-int32 type_vec encoding.
// int64 values 0..63 little-endian -> every odd int32 word == 0.
// ---------------------------------------------------------------------------
__global__ void k_init(const void* __restrict__ tv, long long n) {
    long long idx = (long long)blockIdx.x * blockDim.x + threadIdx.x;
    if (idx < TC) g_acc[idx] = make_float2(0.f, 0.f);
    if (idx < TT) g_cnt[idx] = 0.f;
    if (idx == 0) {
        const int* p = (const int*)tv;
        int lim = (n >= 256) ? 256 : (int)n;
        int is64 = 1;
        for (int i = 1; i < lim; i += 2)
            if (p[i] != 0) { is64 = 0; break; }
        g_is64 = is64;
    }
}

// ---------------------------------------------------------------------------
// Kernel 1: block-wide exclusive-ownership accumulation (RACE-FREE: the whole
// block walks the same row batch; thread t is the only writer of channel t).
//   - float2 table: stride-8B LDS.64/STS.64 is conflict-free (half-warp phases)
//   - double-buffered prefetch: batch n+1 loads issued before batch n RMW
//   - counts kept in a REGISTER (thread t counts ty==t matches): no shared
//     chain, no warp-0 critical path
//   blockDim = 128; dyn smem = TC * 8 = 64KB -> 3 blocks/SM.
// ---------------------------------------------------------------------------
#define ACC_U 16
__global__ void __launch_bounds__(128) k_acc(
    const float* __restrict__ x, const void* __restrict__ tv, long long N)
{
    extern __shared__ float2 sacc[];   // TC entries
    const int tid = threadIdx.x;

    // thread t owns entries i == t (mod 128): no __syncthreads needed anywhere
    #pragma unroll
    for (int i = tid; i < TC; i += 128) sacc[i] = make_float2(0.f, 0.f);

    const int is64 = g_is64;
    const long long* __restrict__ tv64 = (const long long*)tv;
    const int*       __restrict__ tv32 = (const int*)tv;

    const long long stride = (long long)gridDim.x * ACC_U;
    long long base = (long long)blockIdx.x * ACC_U;
    int cntr = 0;

    int   tyA[ACC_U];
    float xvA[ACC_U];

    if (base < N) {
        #pragma unroll
        for (int u = 0; u < ACC_U; u++) {
            long long r = base + u;
            if (r < N) {
                tyA[u] = is64 ? (int)tv64[r] : tv32[r];
                xvA[u] = x[r * CC + tid];
            } else tyA[u] = -1;
        }
    }

    while (base < N) {
        const long long nb = base + stride;
        int   tyB[ACC_U];
        float xvB[ACC_U];

        // Prefetch NEXT batch before touching shared (hides LDG latency
        // behind the serialized RMW chain of the current batch).
        if (nb < N) {
            #pragma unroll
            for (int u = 0; u < ACC_U; u++) {
                long long r = nb + u;
                if (r < N) {
                    tyB[u] = is64 ? (int)tv64[r] : tv32[r];
                    xvB[u] = x[r * CC + tid];
                } else tyB[u] = -1;
            }
        }

        // Exclusive RMW into shared.
        #pragma unroll
        for (int u = 0; u < ACC_U; u++) {
            if (tyA[u] >= 0) {
                int o = tyA[u] * CC + tid;
                float2 a = sacc[o];
                a.x += xvA[u];
                a.y += xvA[u] * xvA[u];
                sacc[o] = a;
                cntr += (tyA[u] == tid);   // register count, pure ALU
            }
        }

        base = nb;
        if (base < N) {
            #pragma unroll
            for (int u = 0; u < ACC_U; u++) { tyA[u] = tyB[u]; xvA[u] = xvB[u]; }
        }
    }

    // Flush: thread reads only the entries it wrote (i == tid mod 128).
    #pragma unroll
    for (int i = tid; i < TC; i += 128) {
        float2 a = sacc[i];
        if (a.x != 0.f || a.y != 0.f) {
            atomicAdd(&g_acc[i].x, a.x);
            atomicAdd(&g_acc[i].y, a.y);
        }
    }
    if (tid < TT && cntr) atomicAdd(&g_cnt[tid], (float)cntr);
}

// ---------------------------------------------------------------------------
// Kernel 2: finalize mean / rstd (cnt clamped >= 1, var clamped >= 0,
// std = sqrt(var + 1e-5)) — matches the reference exactly.
// ---------------------------------------------------------------------------
__global__ void k_fin() {
    int idx = blockIdx.x * blockDim.x + threadIdx.x;
    if (idx >= TC) return;
    int t = idx / CC;
    float cnt  = fmaxf(g_cnt[t], 1.f);
    float2 a   = g_acc[idx];
    float mean = a.x / cnt;
    float var  = fmaxf(a.y / cnt - mean * mean, 0.f);
    g_mean[idx] = mean;
    g_rstd[idx] = 1.f / sqrtf(var + 1e-5f);
}

// ---------------------------------------------------------------------------
// Kernel 3: normalize. Warp-per-row, float4 loads/stores, stats staged in
// shared as SEPARATE mean/rstd tables (conflict-free LDS.128).
//   blockDim = 512 (16 warps), 64KB smem -> 2 blocks/SM (regs) = 50% occ.
// ---------------------------------------------------------------------------
#define NRM_U 4
__global__ void __launch_bounds__(512) k_norm(
    const float* __restrict__ x, const void* __restrict__ tv,
    float* __restrict__ out, long long N)
{
    extern __shared__ float sm[];
    float* smean = sm;        // TC
    float* srstd = sm + TC;   // TC
    const int tid = threadIdx.x;

    #pragma unroll
    for (int i = tid; i < TC; i += 512) {
        smean[i] = g_mean[i];
        srstd[i] = g_rstd[i];
    }
    __syncthreads();

    const int is64 = g_is64;
    const long long* __restrict__ tv64 = (const long long*)tv;
    const int*       __restrict__ tv32 = (const int*)tv;

    const int lane = tid & 31;
    const long long w  = (long long)blockIdx.x * 16 + (tid >> 5);
    const long long nw = (long long)gridDim.x * 16;
    const float4* __restrict__ x4 = (const float4*)x;
    float4* __restrict__ o4 = (float4*)out;

    for (long long r0 = w * NRM_U; r0 < N; r0 += nw * NRM_U) {
        float4 xv[NRM_U];
        int    ty[NRM_U];

        #pragma unroll
        for (int u = 0; u < NRM_U; u++) {
            long long r = r0 + u;
            if (r < N) {
                ty[u] = is64 ? (int)tv64[r] : tv32[r];
                xv[u] = x4[r * (CC / 4) + lane];
            } else ty[u] = -1;
        }
        #pragma unroll
        for (int u = 0; u < NRM_U; u++) {
            if (ty[u] >= 0) {
                int o = ty[u] * CC + 4 * lane;
                float4 mn = *(const float4*)&smean[o];
                float4 rs = *(const float4*)&srstd[o];
                float4 res;
                res.x = (xv[u].x - mn.x) * rs.x;
                res.y = (xv[u].y - mn.y) * rs.y;
                res.z = (xv[u].z - mn.z) * rs.z;
                res.w = (xv[u].w - mn.w) * rs.w;
                o4[(r0 + u) * (CC / 4) + lane] = res;
            }
        }
    }
}

// ---------------------------------------------------------------------------
// Launch
// ---------------------------------------------------------------------------
extern "C" void kernel_launch(void* const* d_in, const int* in_sizes, int n_in,
                              void* d_out, int out_size)
{
    const float* x  = (const float*)d_in[0];
    const void*  tv = d_in[1];
    float* out = (float*)d_out;
    const long long N = (long long)in_sizes[1];   // rows (type_vec length)

    const int ACC_SMEM = TC * (int)sizeof(float2);   // 64 KB
    const int NRM_SMEM = 2 * TC * (int)sizeof(float); // 64 KB

    cudaFuncSetAttribute(k_acc,  cudaFuncAttributeMaxDynamicSharedMemorySize, ACC_SMEM);
    cudaFuncSetAttribute(k_norm, cudaFuncAttributeMaxDynamicSharedMemorySize, NRM_SMEM);

    k_init<<<(TC + 255) / 256, 256>>>(tv, N);
    k_acc <<<444, 128, ACC_SMEM>>>(x, tv, N);       // 148 SMs * 3 blocks
    k_fin <<<(TC + 255) / 256, 256>>>();
    k_norm<<<444, 512, NRM_SMEM>>>(x, tv, out, N);
}

// round 6
// speedup vs baseline: 1.0886x; 1.0886x over previous
#include <cuda_runtime.h>
#include <stdint.h>

#define TT 64          // num types
#define CC 128         // channels
#define TC (TT * CC)   // 8192 stat entries

// ---- device scratch (no allocations allowed) ----
__device__ float2 g_acc[TC];   // {sum, sumsq}
__device__ float  g_cnt[TT];
__device__ float  g_mean[TC];
__device__ float  g_rstd[TC];
__device__ int    g_is64;

// ---------------------------------------------------------------------------
// Kernel 0: zero accumulators + detect int64-vs-int32 type_vec encoding.
// int64 values 0..63 little-endian -> every odd int32 word == 0.
// ---------------------------------------------------------------------------
__global__ void k_init(const void* __restrict__ tv, long long n) {
    long long idx = (long long)blockIdx.x * blockDim.x + threadIdx.x;
    if (idx < TC) g_acc[idx] = make_float2(0.f, 0.f);
    if (idx < TT) g_cnt[idx] = 0.f;
    if (idx == 0) {
        const int* p = (const int*)tv;
        int lim = (n >= 256) ? 256 : (int)n;
        int is64 = 1;
        for (int i = 1; i < lim; i += 2)
            if (p[i] != 0) { is64 = 0; break; }
        g_is64 = is64;
    }
}

// ---------------------------------------------------------------------------
// Kernel 1: block-wide exclusive-ownership accumulation.
//   RACE-FREE: thread t is the only reader/writer of table entries with
//   index % 128 == t, so warps may drift without synchronization.
//   - ping-pong A/B pipeline: next batch's loads issued before this batch's
//     serialized shared-memory RMW chain (which covers DRAM latency)
//   - type ids: ONE tv load per warp-batch (lane u -> row u), shfl fan-out
//   - counts in a register (thread t counts ty==t matches)
//   blockDim = 128; dyn smem = 64KB -> 3 blocks/SM.
// ---------------------------------------------------------------------------
#define ACC_U 16

__global__ void __launch_bounds__(128, 3) k_acc(
    const float* __restrict__ x, const void* __restrict__ tv, long long N)
{
    extern __shared__ float2 sacc[];   // TC entries
    const int tid  = threadIdx.x;
    const int lane = tid & 31;

    #pragma unroll
    for (int i = tid; i < TC; i += 128) sacc[i] = make_float2(0.f, 0.f);

    const int is64 = g_is64;
    const long long* __restrict__ tv64 = (const long long*)tv;
    const int*       __restrict__ tv32 = (const int*)tv;

#define LOADB(TYL, XV, B) do {                                            \
        long long rr = (B) + lane;                                       \
        TYL = -1;                                                         \
        if (lane < ACC_U && rr < N)                                       \
            TYL = is64 ? (int)tv64[rr] : tv32[rr];                        \
        _Pragma("unroll")                                                 \
        for (int u = 0; u < ACC_U; u++) {                                 \
            long long r = (B) + u;                                        \
            XV[u] = (r < N) ? x[r * CC + tid] : 0.f;                      \
        }                                                                 \
    } while (0)

#define RMW(TYL, XV) do {                                                 \
        _Pragma("unroll")                                                 \
        for (int u = 0; u < ACC_U; u++) {                                 \
            int t_u = __shfl_sync(0xffffffffu, TYL, u);                   \
            if (t_u >= 0) {                                               \
                int o = t_u * CC + tid;                                   \
                float2 a = sacc[o];                                       \
                a.x += XV[u];                                             \
                a.y += XV[u] * XV[u];                                     \
                sacc[o] = a;                                              \
                cntr += (t_u == tid);                                     \
            }                                                             \
        }                                                                 \
    } while (0)

    const long long stride = (long long)gridDim.x * ACC_U;
    long long b = (long long)blockIdx.x * ACC_U;
    int cntr = 0;

    int   tylA, tylB;
    float xvA[ACC_U], xvB[ACC_U];

    if (b < N) {
        LOADB(tylA, xvA, b);
        while (b < N) {
            long long b1 = b + stride;
            if (b1 < N) LOADB(tylB, xvB, b1);   // prefetch next
            RMW(tylA, xvA);                      // chain covers DRAM latency
            b = b1;
            if (b >= N) break;
            long long b2 = b + stride;
            if (b2 < N) LOADB(tylA, xvA, b2);
            RMW(tylB, xvB);
            b = b2;
        }
    }
#undef LOADB
#undef RMW

    // Flush: thread reads only the entries it wrote (i % 128 == tid).
    // Skipping zero partials is correctness-neutral (adding 0 is a no-op).
    #pragma unroll
    for (int i = tid; i < TC; i += 128) {
        float2 a = sacc[i];
        if (a.x != 0.f || a.y != 0.f) {
            atomicAdd(&g_acc[i].x, a.x);
            atomicAdd(&g_acc[i].y, a.y);
        }
    }
    if (tid < TT && cntr) atomicAdd(&g_cnt[tid], (float)cntr);
}

// ---------------------------------------------------------------------------
// Kernel 2: finalize mean / rstd (cnt clamped >= 1, var clamped >= 0,
// std = sqrt(var + 1e-5)) — matches the reference exactly.
// ---------------------------------------------------------------------------
__global__ void k_fin() {
    int idx = blockIdx.x * blockDim.x + threadIdx.x;
    if (idx >= TC) return;
    int t = idx / CC;
    float cnt  = fmaxf(g_cnt[t], 1.f);
    float2 a   = g_acc[idx];
    float mean = a.x / cnt;
    float var  = fmaxf(a.y / cnt - mean * mean, 0.f);
    g_mean[idx] = mean;
    g_rstd[idx] = 1.f / sqrtf(var + 1e-5f);
}

// ---------------------------------------------------------------------------
// Kernel 3: normalize (DRAM-bound at ~6.2 TB/s already; unchanged design).
// Warp-per-row, float4 loads/stores, stats staged in shared as SEPARATE
// mean/rstd tables (conflict-free LDS.128). blockDim = 512.
// ---------------------------------------------------------------------------
#define NRM_U 4
__global__ void __launch_bounds__(512) k_norm(
    const float* __restrict__ x, const void* __restrict__ tv,
    float* __restrict__ out, long long N)
{
    extern __shared__ float sm[];
    float* smean = sm;        // TC
    float* srstd = sm + TC;   // TC
    const int tid = threadIdx.x;

    #pragma unroll
    for (int i = tid; i < TC; i += 512) {
        smean[i] = g_mean[i];
        srstd[i] = g_rstd[i];
    }
    __syncthreads();

    const int is64 = g_is64;
    const long long* __restrict__ tv64 = (const long long*)tv;
    const int*       __restrict__ tv32 = (const int*)tv;

    const int lane = tid & 31;
    const long long w  = (long long)blockIdx.x * 16 + (tid >> 5);
    const long long nw = (long long)gridDim.x * 16;
    const float4* __restrict__ x4 = (const float4*)x;
    float4* __restrict__ o4 = (float4*)out;

    for (long long r0 = w * NRM_U; r0 < N; r0 += nw * NRM_U) {
        float4 xv[NRM_U];
        int    ty[NRM_U];

        #pragma unroll
        for (int u = 0; u < NRM_U; u++) {
            long long r = r0 + u;
            if (r < N) {
                ty[u] = is64 ? (int)tv64[r] : tv32[r];
                xv[u] = x4[r * (CC / 4) + lane];
            } else ty[u] = -1;
        }
        #pragma unroll
        for (int u = 0; u < NRM_U; u++) {
            if (ty[u] >= 0) {
                int o = ty[u] * CC + 4 * lane;
                float4 mn = *(const float4*)&smean[o];
                float4 rs = *(const float4*)&srstd[o];
                float4 res;
                res.x = (xv[u].x - mn.x) * rs.x;
                res.y = (xv[u].y - mn.y) * rs.y;
                res.z = (xv[u].z - mn.z) * rs.z;
                res.w = (xv[u].w - mn.w) * rs.w;
                o4[(r0 + u) * (CC / 4) + lane] = res;
            }
        }
    }
}

// ---------------------------------------------------------------------------
// Launch
// ---------------------------------------------------------------------------
extern "C" void kernel_launch(void* const* d_in, const int* in_sizes, int n_in,
                              void* d_out, int out_size)
{
    const float* x  = (const float*)d_in[0];
    const void*  tv = d_in[1];
    float* out = (float*)d_out;
    const long long N = (long long)in_sizes[1];   // rows (type_vec length)

    const int ACC_SMEM = TC * (int)sizeof(float2);    // 64 KB
    const int NRM_SMEM = 2 * TC * (int)sizeof(float); // 64 KB

    cudaFuncSetAttribute(k_acc,  cudaFuncAttributeMaxDynamicSharedMemorySize, ACC_SMEM);
    cudaFuncSetAttribute(k_norm, cudaFuncAttributeMaxDynamicSharedMemorySize, NRM_SMEM);

    k_init<<<(TC + 255) / 256, 256>>>(tv, N);
    k_acc <<<444, 128, ACC_SMEM>>>(x, tv, N);       // 148 SMs * 3 blocks
    k_fin <<<(TC + 255) / 256, 256>>>();
    k_norm<<<444, 512, NRM_SMEM>>>(x, tv, out, N);
}